// round 6
// baseline (speedup 1.0000x reference)
#include <cuda_runtime.h>
#include <cstdint>

// ============================================================
// LinearAttention: out = relu((Xq Wq^T + bq)(Xk Wk^T + bk)^T) (Xv Wv^T + bv)
// B=4, S=2048, D=1024.
// Strategy: 3xTF32 mma.sync GEMMs (fp32-accurate), cp.async double buffer.
//   K1 (x3): proj  NT gemm  M=8192 N=1024 K=1024  (+bias)
//   K2     : score NT gemm  M=2048 N=2048 K=1024  per batch (+relu)
//   K3     : PV    NN gemm  M=2048 N=1024 K=2048  per batch
// ============================================================

#define LDA   20   // smem row stride for [128 x 16] K-major tiles (16+4 pad)
#define LDBN  136  // smem row stride for [16 x 128] N-major tiles (128+8 pad)

// scratch (device globals: allocation-free rule)
__device__ float g_Q[8192 * 1024];
__device__ float g_K[8192 * 1024];
__device__ float g_V[8192 * 1024];
__device__ float g_S[4 * 2048 * 2048];

// ---------------- helpers ----------------
__device__ __forceinline__ void split_tf32(float x, uint32_t& hi, uint32_t& lo) {
    uint32_t h;
    asm("cvt.rna.tf32.f32 %0, %1;" : "=r"(h) : "f"(x));
    float r = x - __uint_as_float(h);
    asm("cvt.rna.tf32.f32 %0, %1;" : "=r"(lo) : "f"(r));
    hi = h;
}

__device__ __forceinline__ void mma8(float* c, const uint32_t* a, const uint32_t* b) {
    asm volatile(
        "mma.sync.aligned.m16n8k8.row.col.f32.tf32.tf32.f32 "
        "{%0,%1,%2,%3},{%4,%5,%6,%7},{%8,%9},{%0,%1,%2,%3};"
        : "+f"(c[0]), "+f"(c[1]), "+f"(c[2]), "+f"(c[3])
        : "r"(a[0]), "r"(a[1]), "r"(a[2]), "r"(a[3]), "r"(b[0]), "r"(b[1]));
}

__device__ __forceinline__ void cp_async16(uint32_t smem, const void* gmem) {
    asm volatile("cp.async.cg.shared.global [%0], [%1], 16;\n" :: "r"(smem), "l"(gmem));
}
__device__ __forceinline__ void cp_commit() { asm volatile("cp.async.commit_group;\n" ::: "memory"); }
template <int N> __device__ __forceinline__ void cp_wait() {
    asm volatile("cp.async.wait_group %0;\n" :: "n"(N) : "memory");
}

// ============================================================
// NT gemm: C[m,n] = sum_k A[m,k]*B[n,k]   (A,B both K-major rows)
// EPI 0: += bias[n];  EPI 1: relu
// ============================================================
template <int EPI>
__global__ void __launch_bounds__(256, 1)
gemm_nt(const float* __restrict__ A, const float* __restrict__ B,
        const float* __restrict__ bias, float* __restrict__ C,
        int M, int N, int K,
        long long aBatch, long long bBatch, long long cBatch)
{
    __shared__ float As[2][128 * LDA];
    __shared__ float Bs[2][128 * LDA];

    A += (long long)blockIdx.z * aBatch;
    B += (long long)blockIdx.z * bBatch;
    C += (long long)blockIdx.z * cBatch;

    const int tid    = threadIdx.x;
    const int lane   = tid & 31;
    const int warp_m = (tid >> 5) >> 1;  // 0..3
    const int warp_n = (tid >> 5) & 1;   // 0..1
    const int gr     = lane >> 2;        // 0..7
    const int tg     = lane & 3;         // 0..3

    const int m0 = blockIdx.y * 128;
    const int n0 = blockIdx.x * 128;

    const int lrow = tid >> 2;  // 0..63
    const int lc4  = tid & 3;

    float c[2][8][4];
#pragma unroll
    for (int i = 0; i < 2; i++)
#pragma unroll
        for (int j = 0; j < 8; j++)
#pragma unroll
            for (int q = 0; q < 4; q++) c[i][j][q] = 0.f;

    const int niter = K / 16;

    auto prefetch = [&](int it) {
        const int kk  = it * 16;
        const int buf = it & 1;
        uint32_t sa = (uint32_t)__cvta_generic_to_shared(&As[buf][0]);
        uint32_t sb = (uint32_t)__cvta_generic_to_shared(&Bs[buf][0]);
#pragma unroll
        for (int h = 0; h < 2; h++) {
            int row = lrow + h * 64;
            cp_async16(sa + (uint32_t)(row * LDA + lc4 * 4) * 4,
                       A + (long long)(m0 + row) * K + kk + lc4 * 4);
            cp_async16(sb + (uint32_t)(row * LDA + lc4 * 4) * 4,
                       B + (long long)(n0 + row) * K + kk + lc4 * 4);
        }
        cp_commit();
    };

    prefetch(0);
    for (int it = 0; it < niter; ++it) {
        if (it + 1 < niter) { prefetch(it + 1); cp_wait<1>(); }
        else                { cp_wait<0>(); }
        __syncthreads();
        const float* as = As[it & 1];
        const float* bs = Bs[it & 1];
#pragma unroll
        for (int k8 = 0; k8 < 2; k8++) {
            const int k0 = k8 * 8;
            uint32_t ah[2][4], al[2][4], bh[8][2], bl[8][2];
#pragma unroll
            for (int mt = 0; mt < 2; mt++) {
                const int r0 = warp_m * 32 + mt * 16;
                split_tf32(as[(r0 + gr    ) * LDA + k0 + tg    ], ah[mt][0], al[mt][0]);
                split_tf32(as[(r0 + gr + 8) * LDA + k0 + tg    ], ah[mt][1], al[mt][1]);
                split_tf32(as[(r0 + gr    ) * LDA + k0 + tg + 4], ah[mt][2], al[mt][2]);
                split_tf32(as[(r0 + gr + 8) * LDA + k0 + tg + 4], ah[mt][3], al[mt][3]);
            }
#pragma unroll
            for (int nt = 0; nt < 8; nt++) {
                const int cn = warp_n * 64 + nt * 8;
                split_tf32(bs[(cn + gr) * LDA + k0 + tg    ], bh[nt][0], bl[nt][0]);
                split_tf32(bs[(cn + gr) * LDA + k0 + tg + 4], bh[nt][1], bl[nt][1]);
            }
#pragma unroll
            for (int mt = 0; mt < 2; mt++)
#pragma unroll
                for (int nt = 0; nt < 8; nt++) {
                    mma8(c[mt][nt], ah[mt], bh[nt]);
                    mma8(c[mt][nt], al[mt], bh[nt]);
                    mma8(c[mt][nt], ah[mt], bl[nt]);
                }
        }
        __syncthreads();
    }

    // epilogue
#pragma unroll
    for (int mt = 0; mt < 2; mt++) {
        const int rbase = m0 + warp_m * 32 + mt * 16 + gr;
#pragma unroll
        for (int nt = 0; nt < 8; nt++) {
            const int cbase = n0 + warp_n * 64 + nt * 8 + 2 * tg;
            float2 v0 = make_float2(c[mt][nt][0], c[mt][nt][1]);
            float2 v1 = make_float2(c[mt][nt][2], c[mt][nt][3]);
            if (EPI == 0) {
                float2 bb = *(const float2*)&bias[cbase];
                v0.x += bb.x; v0.y += bb.y;
                v1.x += bb.x; v1.y += bb.y;
            } else {
                v0.x = fmaxf(v0.x, 0.f); v0.y = fmaxf(v0.y, 0.f);
                v1.x = fmaxf(v1.x, 0.f); v1.y = fmaxf(v1.y, 0.f);
            }
            *(float2*)&C[(long long)rbase * N + cbase]       = v0;
            *(float2*)&C[(long long)(rbase + 8) * N + cbase] = v1;
        }
    }
}

// ============================================================
// NN gemm: C[m,n] = sum_k A[m,k]*B[k,n]
// ============================================================
__global__ void __launch_bounds__(256, 1)
gemm_nn(const float* __restrict__ A, const float* __restrict__ B,
        float* __restrict__ C,
        int M, int N, int K,
        long long aBatch, long long bBatch, long long cBatch)
{
    __shared__ float As[2][128 * LDA];
    __shared__ float Bs[2][16 * LDBN];

    A += (long long)blockIdx.z * aBatch;
    B += (long long)blockIdx.z * bBatch;
    C += (long long)blockIdx.z * cBatch;

    const int tid    = threadIdx.x;
    const int lane   = tid & 31;
    const int warp_m = (tid >> 5) >> 1;
    const int warp_n = (tid >> 5) & 1;
    const int gr     = lane >> 2;
    const int tg     = lane & 3;

    const int m0 = blockIdx.y * 128;
    const int n0 = blockIdx.x * 128;

    const int lrow = tid >> 2;  // A tile: 0..63
    const int lc4  = tid & 3;

    float c[2][8][4];
#pragma unroll
    for (int i = 0; i < 2; i++)
#pragma unroll
        for (int j = 0; j < 8; j++)
#pragma unroll
            for (int q = 0; q < 4; q++) c[i][j][q] = 0.f;

    const int niter = K / 16;

    auto prefetch = [&](int it) {
        const int kk  = it * 16;
        const int buf = it & 1;
        uint32_t sa = (uint32_t)__cvta_generic_to_shared(&As[buf][0]);
        uint32_t sb = (uint32_t)__cvta_generic_to_shared(&Bs[buf][0]);
#pragma unroll
        for (int h = 0; h < 2; h++) {
            int arow = lrow + h * 64;
            cp_async16(sa + (uint32_t)(arow * LDA + lc4 * 4) * 4,
                       A + (long long)(m0 + arow) * K + kk + lc4 * 4);
            int idx  = tid + h * 256;        // 512 float4 of B tile
            int brow = idx >> 5;             // 0..15 (k)
            int bc4  = idx & 31;             // 0..31 (n/4)
            cp_async16(sb + (uint32_t)(brow * LDBN + bc4 * 4) * 4,
                       B + (long long)(kk + brow) * N + n0 + bc4 * 4);
        }
        cp_commit();
    };

    prefetch(0);
    for (int it = 0; it < niter; ++it) {
        if (it + 1 < niter) { prefetch(it + 1); cp_wait<1>(); }
        else                { cp_wait<0>(); }
        __syncthreads();
        const float* as = As[it & 1];
        const float* bs = Bs[it & 1];
#pragma unroll
        for (int k8 = 0; k8 < 2; k8++) {
            const int k0 = k8 * 8;
            uint32_t ah[2][4], al[2][4], bh[8][2], bl[8][2];
#pragma unroll
            for (int mt = 0; mt < 2; mt++) {
                const int r0 = warp_m * 32 + mt * 16;
                split_tf32(as[(r0 + gr    ) * LDA + k0 + tg    ], ah[mt][0], al[mt][0]);
                split_tf32(as[(r0 + gr + 8) * LDA + k0 + tg    ], ah[mt][1], al[mt][1]);
                split_tf32(as[(r0 + gr    ) * LDA + k0 + tg + 4], ah[mt][2], al[mt][2]);
                split_tf32(as[(r0 + gr + 8) * LDA + k0 + tg + 4], ah[mt][3], al[mt][3]);
            }
#pragma unroll
            for (int nt = 0; nt < 8; nt++) {
                const int cn = warp_n * 64 + nt * 8;
                split_tf32(bs[(k0 + tg    ) * LDBN + cn + gr], bh[nt][0], bl[nt][0]);
                split_tf32(bs[(k0 + tg + 4) * LDBN + cn + gr], bh[nt][1], bl[nt][1]);
            }
#pragma unroll
            for (int mt = 0; mt < 2; mt++)
#pragma unroll
                for (int nt = 0; nt < 8; nt++) {
                    mma8(c[mt][nt], ah[mt], bh[nt]);
                    mma8(c[mt][nt], al[mt], bh[nt]);
                    mma8(c[mt][nt], ah[mt], bl[nt]);
                }
        }
        __syncthreads();
    }

#pragma unroll
    for (int mt = 0; mt < 2; mt++) {
        const int rbase = m0 + warp_m * 32 + mt * 16 + gr;
#pragma unroll
        for (int nt = 0; nt < 8; nt++) {
            const int cbase = n0 + warp_n * 64 + nt * 8 + 2 * tg;
            *(float2*)&C[(long long)rbase * N + cbase]       = make_float2(c[mt][nt][0], c[mt][nt][1]);
            *(float2*)&C[(long long)(rbase + 8) * N + cbase] = make_float2(c[mt][nt][2], c[mt][nt][3]);
        }
    }
}

// ============================================================
// launch
// ============================================================
extern "C" void kernel_launch(void* const* d_in, const int* in_sizes, int n_in,
                              void* d_out, int out_size)
{
    const float* q  = (const float*)d_in[0];
    const float* k  = (const float*)d_in[1];
    const float* v  = (const float*)d_in[2];
    const float* Wq = (const float*)d_in[3];
    const float* bq = (const float*)d_in[4];
    const float* Wk = (const float*)d_in[5];
    const float* bk = (const float*)d_in[6];
    const float* Wv = (const float*)d_in[7];
    const float* bv = (const float*)d_in[8];
    float* out = (float*)d_out;

    float *gQ, *gK, *gV, *gS;
    cudaGetSymbolAddress((void**)&gQ, g_Q);
    cudaGetSymbolAddress((void**)&gK, g_K);
    cudaGetSymbolAddress((void**)&gV, g_V);
    cudaGetSymbolAddress((void**)&gS, g_S);

    dim3 block(256);

    // projections: M=8192, N=1024, K=1024
    gemm_nt<0><<<dim3(8, 64, 1), block>>>(q, Wq, bq, gQ, 8192, 1024, 1024, 0, 0, 0);
    gemm_nt<0><<<dim3(8, 64, 1), block>>>(k, Wk, bk, gK, 8192, 1024, 1024, 0, 0, 0);
    gemm_nt<0><<<dim3(8, 64, 1), block>>>(v, Wv, bv, gV, 8192, 1024, 1024, 0, 0, 0);

    // scores = relu(Q K^T): per batch M=2048, N=2048, K=1024
    gemm_nt<1><<<dim3(16, 16, 4), block>>>(gQ, gK, nullptr, gS,
                                           2048, 2048, 1024,
                                           2048LL * 1024, 2048LL * 1024, 2048LL * 2048);

    // out = scores @ V: per batch M=2048, N=1024, K=2048
    gemm_nn<<<dim3(8, 16, 4), block>>>(gS, gV, out,
                                       2048, 1024, 2048,
                                       2048LL * 2048, 2048LL * 1024, 2048LL * 1024);
}

// round 7
// speedup vs baseline: 1.0009x; 1.0009x over previous
#include <cuda_runtime.h>
#include <cstdint>

// ============================================================
// LinearAttention: out = relu((Xq Wq^T + bq)(Xk Wk^T + bk)^T) (Xv Wv^T + bv)
// B=4, S=2048, D=1024.
// Strategy: 3xTF32 mma.sync GEMMs (fp32-accurate), cp.async double buffer.
//   K1 (x3): proj  NT gemm  M=8192 N=1024 K=1024  (+bias)
//   K2     : score NT gemm  M=2048 N=2048 K=1024  per batch (+relu)
//   K3     : PV    NN gemm  M=2048 N=1024 K=2048  per batch
// ============================================================

#define LDA   20   // smem row stride for [128 x 16] K-major tiles (16+4 pad)
#define LDBN  136  // smem row stride for [16 x 128] N-major tiles (128+8 pad)

// scratch (device globals: allocation-free rule)
__device__ float g_Q[8192 * 1024];
__device__ float g_K[8192 * 1024];
__device__ float g_V[8192 * 1024];
__device__ float g_S[4 * 2048 * 2048];

// ---------------- helpers ----------------
__device__ __forceinline__ void split_tf32(float x, uint32_t& hi, uint32_t& lo) {
    uint32_t h;
    asm("cvt.rna.tf32.f32 %0, %1;" : "=r"(h) : "f"(x));
    float r = x - __uint_as_float(h);
    asm("cvt.rna.tf32.f32 %0, %1;" : "=r"(lo) : "f"(r));
    hi = h;
}

__device__ __forceinline__ void mma8(float* c, const uint32_t* a, const uint32_t* b) {
    asm volatile(
        "mma.sync.aligned.m16n8k8.row.col.f32.tf32.tf32.f32 "
        "{%0,%1,%2,%3},{%4,%5,%6,%7},{%8,%9},{%0,%1,%2,%3};"
        : "+f"(c[0]), "+f"(c[1]), "+f"(c[2]), "+f"(c[3])
        : "r"(a[0]), "r"(a[1]), "r"(a[2]), "r"(a[3]), "r"(b[0]), "r"(b[1]));
}

__device__ __forceinline__ void cp_async16(uint32_t smem, const void* gmem) {
    asm volatile("cp.async.cg.shared.global [%0], [%1], 16;\n" :: "r"(smem), "l"(gmem));
}
__device__ __forceinline__ void cp_commit() { asm volatile("cp.async.commit_group;\n" ::: "memory"); }
template <int N> __device__ __forceinline__ void cp_wait() {
    asm volatile("cp.async.wait_group %0;\n" :: "n"(N) : "memory");
}

// ============================================================
// NT gemm: C[m,n] = sum_k A[m,k]*B[n,k]   (A,B both K-major rows)
// EPI 0: += bias[n];  EPI 1: relu
// ============================================================
template <int EPI>
__global__ void __launch_bounds__(256, 1)
gemm_nt(const float* __restrict__ A, const float* __restrict__ B,
        const float* __restrict__ bias, float* __restrict__ C,
        int M, int N, int K,
        long long aBatch, long long bBatch, long long cBatch)
{
    __shared__ float As[2][128 * LDA];
    __shared__ float Bs[2][128 * LDA];

    A += (long long)blockIdx.z * aBatch;
    B += (long long)blockIdx.z * bBatch;
    C += (long long)blockIdx.z * cBatch;

    const int tid    = threadIdx.x;
    const int lane   = tid & 31;
    const int warp_m = (tid >> 5) >> 1;  // 0..3
    const int warp_n = (tid >> 5) & 1;   // 0..1
    const int gr     = lane >> 2;        // 0..7
    const int tg     = lane & 3;         // 0..3

    const int m0 = blockIdx.y * 128;
    const int n0 = blockIdx.x * 128;

    const int lrow = tid >> 2;  // 0..63
    const int lc4  = tid & 3;

    float c[2][8][4];
#pragma unroll
    for (int i = 0; i < 2; i++)
#pragma unroll
        for (int j = 0; j < 8; j++)
#pragma unroll
            for (int q = 0; q < 4; q++) c[i][j][q] = 0.f;

    const int niter = K / 16;

    auto prefetch = [&](int it) {
        const int kk  = it * 16;
        const int buf = it & 1;
        uint32_t sa = (uint32_t)__cvta_generic_to_shared(&As[buf][0]);
        uint32_t sb = (uint32_t)__cvta_generic_to_shared(&Bs[buf][0]);
#pragma unroll
        for (int h = 0; h < 2; h++) {
            int row = lrow + h * 64;
            cp_async16(sa + (uint32_t)(row * LDA + lc4 * 4) * 4,
                       A + (long long)(m0 + row) * K + kk + lc4 * 4);
            cp_async16(sb + (uint32_t)(row * LDA + lc4 * 4) * 4,
                       B + (long long)(n0 + row) * K + kk + lc4 * 4);
        }
        cp_commit();
    };

    prefetch(0);
    for (int it = 0; it < niter; ++it) {
        if (it + 1 < niter) { prefetch(it + 1); cp_wait<1>(); }
        else                { cp_wait<0>(); }
        __syncthreads();
        const float* as = As[it & 1];
        const float* bs = Bs[it & 1];
#pragma unroll
        for (int k8 = 0; k8 < 2; k8++) {
            const int k0 = k8 * 8;
            uint32_t ah[2][4], al[2][4], bh[8][2], bl[8][2];
#pragma unroll
            for (int mt = 0; mt < 2; mt++) {
                const int r0 = warp_m * 32 + mt * 16;
                split_tf32(as[(r0 + gr    ) * LDA + k0 + tg    ], ah[mt][0], al[mt][0]);
                split_tf32(as[(r0 + gr + 8) * LDA + k0 + tg    ], ah[mt][1], al[mt][1]);
                split_tf32(as[(r0 + gr    ) * LDA + k0 + tg + 4], ah[mt][2], al[mt][2]);
                split_tf32(as[(r0 + gr + 8) * LDA + k0 + tg + 4], ah[mt][3], al[mt][3]);
            }
#pragma unroll
            for (int nt = 0; nt < 8; nt++) {
                const int cn = warp_n * 64 + nt * 8;
                split_tf32(bs[(cn + gr) * LDA + k0 + tg    ], bh[nt][0], bl[nt][0]);
                split_tf32(bs[(cn + gr) * LDA + k0 + tg + 4], bh[nt][1], bl[nt][1]);
            }
#pragma unroll
            for (int mt = 0; mt < 2; mt++)
#pragma unroll
                for (int nt = 0; nt < 8; nt++) {
                    mma8(c[mt][nt], ah[mt], bh[nt]);
                    mma8(c[mt][nt], al[mt], bh[nt]);
                    mma8(c[mt][nt], ah[mt], bl[nt]);
                }
        }
        __syncthreads();
    }

    // epilogue
#pragma unroll
    for (int mt = 0; mt < 2; mt++) {
        const int rbase = m0 + warp_m * 32 + mt * 16 + gr;
#pragma unroll
        for (int nt = 0; nt < 8; nt++) {
            const int cbase = n0 + warp_n * 64 + nt * 8 + 2 * tg;
            float2 v0 = make_float2(c[mt][nt][0], c[mt][nt][1]);
            float2 v1 = make_float2(c[mt][nt][2], c[mt][nt][3]);
            if (EPI == 0) {
                float2 bb = *(const float2*)&bias[cbase];
                v0.x += bb.x; v0.y += bb.y;
                v1.x += bb.x; v1.y += bb.y;
            } else {
                v0.x = fmaxf(v0.x, 0.f); v0.y = fmaxf(v0.y, 0.f);
                v1.x = fmaxf(v1.x, 0.f); v1.y = fmaxf(v1.y, 0.f);
            }
            *(float2*)&C[(long long)rbase * N + cbase]       = v0;
            *(float2*)&C[(long long)(rbase + 8) * N + cbase] = v1;
        }
    }
}

// ============================================================
// NN gemm: C[m,n] = sum_k A[m,k]*B[k,n]
// ============================================================
__global__ void __launch_bounds__(256, 1)
gemm_nn(const float* __restrict__ A, const float* __restrict__ B,
        float* __restrict__ C,
        int M, int N, int K,
        long long aBatch, long long bBatch, long long cBatch)
{
    __shared__ float As[2][128 * LDA];
    __shared__ float Bs[2][16 * LDBN];

    A += (long long)blockIdx.z * aBatch;
    B += (long long)blockIdx.z * bBatch;
    C += (long long)blockIdx.z * cBatch;

    const int tid    = threadIdx.x;
    const int lane   = tid & 31;
    const int warp_m = (tid >> 5) >> 1;
    const int warp_n = (tid >> 5) & 1;
    const int gr     = lane >> 2;
    const int tg     = lane & 3;

    const int m0 = blockIdx.y * 128;
    const int n0 = blockIdx.x * 128;

    const int lrow = tid >> 2;  // A tile: 0..63
    const int lc4  = tid & 3;

    float c[2][8][4];
#pragma unroll
    for (int i = 0; i < 2; i++)
#pragma unroll
        for (int j = 0; j < 8; j++)
#pragma unroll
            for (int q = 0; q < 4; q++) c[i][j][q] = 0.f;

    const int niter = K / 16;

    auto prefetch = [&](int it) {
        const int kk  = it * 16;
        const int buf = it & 1;
        uint32_t sa = (uint32_t)__cvta_generic_to_shared(&As[buf][0]);
        uint32_t sb = (uint32_t)__cvta_generic_to_shared(&Bs[buf][0]);
#pragma unroll
        for (int h = 0; h < 2; h++) {
            int arow = lrow + h * 64;
            cp_async16(sa + (uint32_t)(arow * LDA + lc4 * 4) * 4,
                       A + (long long)(m0 + arow) * K + kk + lc4 * 4);
            int idx  = tid + h * 256;        // 512 float4 of B tile
            int brow = idx >> 5;             // 0..15 (k)
            int bc4  = idx & 31;             // 0..31 (n/4)
            cp_async16(sb + (uint32_t)(brow * LDBN + bc4 * 4) * 4,
                       B + (long long)(kk + brow) * N + n0 + bc4 * 4);
        }
        cp_commit();
    };

    prefetch(0);
    for (int it = 0; it < niter; ++it) {
        if (it + 1 < niter) { prefetch(it + 1); cp_wait<1>(); }
        else                { cp_wait<0>(); }
        __syncthreads();
        const float* as = As[it & 1];
        const float* bs = Bs[it & 1];
#pragma unroll
        for (int k8 = 0; k8 < 2; k8++) {
            const int k0 = k8 * 8;
            uint32_t ah[2][4], al[2][4], bh[8][2], bl[8][2];
#pragma unroll
            for (int mt = 0; mt < 2; mt++) {
                const int r0 = warp_m * 32 + mt * 16;
                split_tf32(as[(r0 + gr    ) * LDA + k0 + tg    ], ah[mt][0], al[mt][0]);
                split_tf32(as[(r0 + gr + 8) * LDA + k0 + tg    ], ah[mt][1], al[mt][1]);
                split_tf32(as[(r0 + gr    ) * LDA + k0 + tg + 4], ah[mt][2], al[mt][2]);
                split_tf32(as[(r0 + gr + 8) * LDA + k0 + tg + 4], ah[mt][3], al[mt][3]);
            }
#pragma unroll
            for (int nt = 0; nt < 8; nt++) {
                const int cn = warp_n * 64 + nt * 8;
                split_tf32(bs[(k0 + tg    ) * LDBN + cn + gr], bh[nt][0], bl[nt][0]);
                split_tf32(bs[(k0 + tg + 4) * LDBN + cn + gr], bh[nt][1], bl[nt][1]);
            }
#pragma unroll
            for (int mt = 0; mt < 2; mt++)
#pragma unroll
                for (int nt = 0; nt < 8; nt++) {
                    mma8(c[mt][nt], ah[mt], bh[nt]);
                    mma8(c[mt][nt], al[mt], bh[nt]);
                    mma8(c[mt][nt], ah[mt], bl[nt]);
                }
        }
        __syncthreads();
    }

#pragma unroll
    for (int mt = 0; mt < 2; mt++) {
        const int rbase = m0 + warp_m * 32 + mt * 16 + gr;
#pragma unroll
        for (int nt = 0; nt < 8; nt++) {
            const int cbase = n0 + warp_n * 64 + nt * 8 + 2 * tg;
            *(float2*)&C[(long long)rbase * N + cbase]       = make_float2(c[mt][nt][0], c[mt][nt][1]);
            *(float2*)&C[(long long)(rbase + 8) * N + cbase] = make_float2(c[mt][nt][2], c[mt][nt][3]);
        }
    }
}

// ============================================================
// launch
// ============================================================
extern "C" void kernel_launch(void* const* d_in, const int* in_sizes, int n_in,
                              void* d_out, int out_size)
{
    const float* q  = (const float*)d_in[0];
    const float* k  = (const float*)d_in[1];
    const float* v  = (const float*)d_in[2];
    const float* Wq = (const float*)d_in[3];
    const float* bq = (const float*)d_in[4];
    const float* Wk = (const float*)d_in[5];
    const float* bk = (const float*)d_in[6];
    const float* Wv = (const float*)d_in[7];
    const float* bv = (const float*)d_in[8];
    float* out = (float*)d_out;

    float *gQ, *gK, *gV, *gS;
    cudaGetSymbolAddress((void**)&gQ, g_Q);
    cudaGetSymbolAddress((void**)&gK, g_K);
    cudaGetSymbolAddress((void**)&gV, g_V);
    cudaGetSymbolAddress((void**)&gS, g_S);

    dim3 block(256);

    // projections: M=8192, N=1024, K=1024
    gemm_nt<0><<<dim3(8, 64, 1), block>>>(q, Wq, bq, gQ, 8192, 1024, 1024, 0, 0, 0);
    gemm_nt<0><<<dim3(8, 64, 1), block>>>(k, Wk, bk, gK, 8192, 1024, 1024, 0, 0, 0);
    gemm_nt<0><<<dim3(8, 64, 1), block>>>(v, Wv, bv, gV, 8192, 1024, 1024, 0, 0, 0);

    // scores = relu(Q K^T): per batch M=2048, N=2048, K=1024
    gemm_nt<1><<<dim3(16, 16, 4), block>>>(gQ, gK, nullptr, gS,
                                           2048, 2048, 1024,
                                           2048LL * 1024, 2048LL * 1024, 2048LL * 2048);

    // out = scores @ V: per batch M=2048, N=1024, K=2048
    gemm_nn<<<dim3(8, 16, 4), block>>>(gS, gV, out,
                                       2048, 1024, 2048,
                                       2048LL * 2048, 2048LL * 1024, 2048LL * 1024);
}